// round 7
// baseline (speedup 1.0000x reference)
#include <cuda_runtime.h>
#include <cuda_bf16.h>
#include <cstdint>
#include <cstdio>

// Problem constants
#define S_   1024
#define B_   8
#define H_   1024
#define NH_  16
#define DK_  64
#define BH_  (NH_ * B_)        // 128
#define M_   (S_ * B_)         // 8192 rows for projection GEMMs

static const size_t OUT_ELEMS  = (size_t)S_ * B_ * H_;          // 8,388,608
static const size_t DIST_ELEMS = (size_t)BH_ * S_ * S_;         // 134,217,728

// Scratch (device globals; allocation-free per harness rules)
__device__ float g_Q[(size_t)BH_ * S_ * DK_];   // [bh][s][d]
__device__ float g_K[(size_t)BH_ * S_ * DK_];
__device__ float g_V[(size_t)BH_ * S_ * DK_];
__device__ float g_att[(size_t)M_ * H_];        // [(b*S+s)][h]
__device__ float g_dist_fallback[(size_t)BH_ * S_ * S_];  // 512MB fallback if d_out only holds `out`

// ---------------------------------------------------------------------------
// GEMM: C[r,o] = sum_h A[r,h] * W[o,h]   (A: M_ x 1024 row-major, W: 1024x1024 row-major)
// mode 0: projection scatter  -> out[((head*B+b)*S + s)*64 + d],  r=s*B+b, o=head*64+d
// mode 1: final out transpose -> out[(s*B+b)*H + o],              r=b*S+s
// BM=BN=128, BK=8, 256 threads, 8x8 per thread.
// ---------------------------------------------------------------------------
__global__ __launch_bounds__(256, 1)
void gemm_abT_kernel(const float* __restrict__ A, const float* __restrict__ W,
                     float* __restrict__ out, int mode)
{
    __shared__ float As[8][128];
    __shared__ float Bs[8][128];

    const int tid  = threadIdx.x;
    const int tx   = tid & 15;   // 0..15  (cols)
    const int ty   = tid >> 4;   // 0..15  (rows)
    const int brow = blockIdx.y * 128;
    const int bcol = blockIdx.x * 128;

    const int lrow = tid >> 1;          // 0..127
    const int lcol = (tid & 1) * 4;     // 0 or 4

    const float* Aptr = A + (size_t)(brow + lrow) * H_ + lcol;
    const float* Wptr = W + (size_t)(bcol + lrow) * H_ + lcol;

    float acc[8][8];
#pragma unroll
    for (int i = 0; i < 8; i++)
#pragma unroll
        for (int j = 0; j < 8; j++) acc[i][j] = 0.0f;

    for (int k0 = 0; k0 < H_; k0 += 8) {
        float4 av = *(const float4*)(Aptr + k0);
        float4 bv = *(const float4*)(Wptr + k0);
        As[lcol + 0][lrow] = av.x; As[lcol + 1][lrow] = av.y;
        As[lcol + 2][lrow] = av.z; As[lcol + 3][lrow] = av.w;
        Bs[lcol + 0][lrow] = bv.x; Bs[lcol + 1][lrow] = bv.y;
        Bs[lcol + 2][lrow] = bv.z; Bs[lcol + 3][lrow] = bv.w;
        __syncthreads();
#pragma unroll
        for (int k = 0; k < 8; k++) {
            float ra[8], rb[8];
#pragma unroll
            for (int i = 0; i < 8; i++) ra[i] = As[k][ty * 8 + i];
#pragma unroll
            for (int j = 0; j < 8; j++) rb[j] = Bs[k][tx * 8 + j];
#pragma unroll
            for (int i = 0; i < 8; i++)
#pragma unroll
                for (int j = 0; j < 8; j++)
                    acc[i][j] = fmaf(ra[i], rb[j], acc[i][j]);
        }
        __syncthreads();
    }

#pragma unroll
    for (int i = 0; i < 8; i++) {
        const int r = brow + ty * 8 + i;
#pragma unroll
        for (int j = 0; j < 8; j++) {
            const int o = bcol + tx * 8 + j;
            const float v = acc[i][j];
            if (mode == 0) {
                const int s = r >> 3, b = r & 7;           // r = s*B + b
                const int head = o >> 6, d = o & 63;
                out[(((size_t)(head * B_ + b)) * S_ + s) * DK_ + d] = v;
            } else {
                const int b = r >> 10, s = r & 1023;       // r = b*S + s
                out[((size_t)s * B_ + b) * H_ + o] = v;
            }
        }
    }
}

// ---------------------------------------------------------------------------
// Scores: raw[bh,i,j] = 0.125 * dot(K[bh,i,:], Q[bh,j,:]) ; only tiles with j<=i
// 64x64 tiles over (i,j), K-dim = 64 in 4 steps of 16. Upper-triangular tiles skipped.
// ---------------------------------------------------------------------------
__global__ __launch_bounds__(256, 1)
void scores_kernel(const float* __restrict__ Qb, const float* __restrict__ Kb,
                   float* __restrict__ dist)
{
    const int jb = blockIdx.x;   // 0..15
    const int ib = blockIdx.y;   // 0..15
    const int bh = blockIdx.z;   // 0..127
    if (jb > ib) return;         // fully masked tile: softmax writes zeros there

    __shared__ float Ks[64][17];
    __shared__ float Qs[64][17];

    const float* Kbase = Kb + (size_t)bh * S_ * DK_;
    const float* Qbase = Qb + (size_t)bh * S_ * DK_;

    const int tid  = threadIdx.x;
    const int lrow = tid >> 2;          // 0..63
    const int lcol = (tid & 3) * 4;     // 0,4,8,12
    const int tx   = tid & 15;
    const int ty   = tid >> 4;

    float acc[4][4];
#pragma unroll
    for (int i = 0; i < 4; i++)
#pragma unroll
        for (int j = 0; j < 4; j++) acc[i][j] = 0.0f;

    for (int k0 = 0; k0 < DK_; k0 += 16) {
        float4 kv = *(const float4*)(Kbase + (size_t)(ib * 64 + lrow) * DK_ + k0 + lcol);
        float4 qv = *(const float4*)(Qbase + (size_t)(jb * 64 + lrow) * DK_ + k0 + lcol);
        Ks[lrow][lcol + 0] = kv.x; Ks[lrow][lcol + 1] = kv.y;
        Ks[lrow][lcol + 2] = kv.z; Ks[lrow][lcol + 3] = kv.w;
        Qs[lrow][lcol + 0] = qv.x; Qs[lrow][lcol + 1] = qv.y;
        Qs[lrow][lcol + 2] = qv.z; Qs[lrow][lcol + 3] = qv.w;
        __syncthreads();
#pragma unroll
        for (int k = 0; k < 16; k++) {
            float ra[4], rb[4];
#pragma unroll
            for (int ii = 0; ii < 4; ii++) ra[ii] = Ks[ty * 4 + ii][k];
#pragma unroll
            for (int jj = 0; jj < 4; jj++) rb[jj] = Qs[tx * 4 + jj][k];
#pragma unroll
            for (int ii = 0; ii < 4; ii++)
#pragma unroll
                for (int jj = 0; jj < 4; jj++)
                    acc[ii][jj] = fmaf(ra[ii], rb[jj], acc[ii][jj]);
        }
        __syncthreads();
    }

#pragma unroll
    for (int ii = 0; ii < 4; ii++) {
        const int i = ib * 64 + ty * 4 + ii;
        float* rowp = dist + (size_t)bh * S_ * S_ + (size_t)i * S_ + jb * 64;
#pragma unroll
        for (int jj = 0; jj < 4; jj++)
            rowp[tx * 4 + jj] = acc[ii][jj] * 0.125f;
    }
}

// ---------------------------------------------------------------------------
// Softmax over j (query axis) for each (bh, i), valid range j in [0, i].
// Writes the FULL row: normalized values for j<=i, exact 0 for j>i.
// ---------------------------------------------------------------------------
__global__ __launch_bounds__(256, 1)
void softmax_kernel(float* __restrict__ dist)
{
    const int i  = blockIdx.x;
    const int bh = blockIdx.y;
    float* row = dist + (size_t)bh * S_ * S_ + (size_t)i * S_;
    const int n = i + 1;
    const int tid = threadIdx.x;

    float x[4];
    float mx = -INFINITY;
#pragma unroll
    for (int t = 0; t < 4; t++) {
        const int j = tid + t * 256;
        x[t] = (j < n) ? row[j] : -INFINITY;
        mx = fmaxf(mx, x[t]);
    }
#pragma unroll
    for (int o = 16; o; o >>= 1) mx = fmaxf(mx, __shfl_xor_sync(0xFFFFFFFFu, mx, o));

    __shared__ float red[8];
    if ((tid & 31) == 0) red[tid >> 5] = mx;
    __syncthreads();
    float bmax = red[0];
#pragma unroll
    for (int w = 1; w < 8; w++) bmax = fmaxf(bmax, red[w]);
    __syncthreads();

    float e[4];
    float s = 0.0f;
#pragma unroll
    for (int t = 0; t < 4; t++) {
        const int j = tid + t * 256;
        e[t] = (j < n) ? __expf(x[t] - bmax) : 0.0f;
        s += e[t];
    }
#pragma unroll
    for (int o = 16; o; o >>= 1) s += __shfl_xor_sync(0xFFFFFFFFu, s, o);
    if ((tid & 31) == 0) red[tid >> 5] = s;
    __syncthreads();
    float bsum = red[0];
#pragma unroll
    for (int w = 1; w < 8; w++) bsum += red[w];

    const float inv = 1.0f / bsum;
#pragma unroll
    for (int t = 0; t < 4; t++) {
        const int j = tid + t * 256;
        row[j] = e[t] * inv;
    }
}

// ---------------------------------------------------------------------------
// att[j,bh,d] = sum_i dist[bh,i,j] * V[bh,i,d]; nonzero only for i >= j, so the
// K-loop starts at the tile diagonal. Output scattered to g_att[(b*S+j)][head*64+d].
// ---------------------------------------------------------------------------
__global__ __launch_bounds__(256, 1)
void att_kernel(const float* __restrict__ dist, const float* __restrict__ Vb,
                float* __restrict__ att)
{
    const int jb = blockIdx.x;   // 0..15
    const int bh = blockIdx.y;   // 0..127

    __shared__ float Ds[16][68];
    __shared__ float Vs[16][68];

    const float* dbase = dist + (size_t)bh * S_ * S_;
    const float* vbase = Vb + (size_t)bh * S_ * DK_;

    const int tid  = threadIdx.x;
    const int lrow = tid >> 4;          // 0..15
    const int lcol = (tid & 15) * 4;    // 0..60
    const int tx   = tid & 15;
    const int ty   = tid >> 4;

    float acc[4][4];
#pragma unroll
    for (int i = 0; i < 4; i++)
#pragma unroll
        for (int j = 0; j < 4; j++) acc[i][j] = 0.0f;

    for (int k0 = jb * 64; k0 < S_; k0 += 16) {
        float4 dv = *(const float4*)(dbase + (size_t)(k0 + lrow) * S_ + jb * 64 + lcol);
        float4 vv = *(const float4*)(vbase + (size_t)(k0 + lrow) * DK_ + lcol);
        Ds[lrow][lcol + 0] = dv.x; Ds[lrow][lcol + 1] = dv.y;
        Ds[lrow][lcol + 2] = dv.z; Ds[lrow][lcol + 3] = dv.w;
        Vs[lrow][lcol + 0] = vv.x; Vs[lrow][lcol + 1] = vv.y;
        Vs[lrow][lcol + 2] = vv.z; Vs[lrow][lcol + 3] = vv.w;
        __syncthreads();
#pragma unroll
        for (int k = 0; k < 16; k++) {
            float ra[4], rb[4];
#pragma unroll
            for (int ii = 0; ii < 4; ii++) ra[ii] = Ds[k][ty * 4 + ii];
#pragma unroll
            for (int dd = 0; dd < 4; dd++) rb[dd] = Vs[k][tx * 4 + dd];
#pragma unroll
            for (int ii = 0; ii < 4; ii++)
#pragma unroll
                for (int dd = 0; dd < 4; dd++)
                    acc[ii][dd] = fmaf(ra[ii], rb[dd], acc[ii][dd]);
        }
        __syncthreads();
    }

    const int head = bh >> 3, b = bh & 7;
#pragma unroll
    for (int ii = 0; ii < 4; ii++) {
        const int j = jb * 64 + ty * 4 + ii;
        float* op = att + ((size_t)b * S_ + j) * H_ + head * DK_;
#pragma unroll
        for (int dd = 0; dd < 4; dd++)
            op[tx * 4 + dd] = acc[ii][dd];
    }
}

// ---------------------------------------------------------------------------
extern "C" void kernel_launch(void* const* d_in, const int* in_sizes, int n_in,
                              void* d_out, int out_size)
{
    const float* value = (const float*)d_in[0];
    const float* key   = (const float*)d_in[1];
    const float* query = (const float*)d_in[2];
    const float* Wq    = (const float*)d_in[3];
    const float* Wk    = (const float*)d_in[4];
    const float* Wv    = (const float*)d_in[5];
    const float* Wo    = (const float*)d_in[6];
    float* out = (float*)d_out;

    // scratch pointers via symbols
    float *qp, *kp, *vp, *ap, *distFb;
    cudaGetSymbolAddress((void**)&qp, g_Q);
    cudaGetSymbolAddress((void**)&kp, g_K);
    cudaGetSymbolAddress((void**)&vp, g_V);
    cudaGetSymbolAddress((void**)&ap, g_att);
    cudaGetSymbolAddress((void**)&distFb, g_dist_fallback);

    // dist target: second tuple element lives right after `out` if out_size covers it
    float* dist = ((size_t)out_size >= OUT_ELEMS + DIST_ELEMS) ? (out + OUT_ELEMS) : distFb;

    dim3 gGemm(H_ / 128, M_ / 128);      // (8, 64)

    // Projections
    gemm_abT_kernel<<<gGemm, 256>>>(query, Wq, qp, 0);
    gemm_abT_kernel<<<gGemm, 256>>>(key,   Wk, kp, 0);
    gemm_abT_kernel<<<gGemm, 256>>>(value, Wv, vp, 0);

    // Scores (masked tiles skipped) + softmax over query axis
    scores_kernel<<<dim3(16, 16, BH_), 256>>>(qp, kp, dist);
    softmax_kernel<<<dim3(S_, BH_), 256>>>(dist);

    // att = dist^T @ V per head-batch
    att_kernel<<<dim3(16, BH_), 256>>>(dist, vp, ap);

    // out = att @ Wo^T, written transposed to (S,B,H)
    gemm_abT_kernel<<<gGemm, 256>>>(ap, Wo, out, 1);
}

// round 8
// speedup vs baseline: 1.0018x; 1.0018x over previous
#include <cuda_runtime.h>
#include <cuda_bf16.h>
#include <cstdint>
#include <cstdio>

// Problem constants
#define S_   1024
#define B_   8
#define H_   1024
#define NH_  16
#define DK_  64
#define BH_  (NH_ * B_)        // 128
#define M_   (S_ * B_)         // 8192 rows for projection GEMMs

static const size_t OUT_ELEMS  = (size_t)S_ * B_ * H_;          // 8,388,608
static const size_t DIST_ELEMS = (size_t)BH_ * S_ * S_;         // 134,217,728

// Scratch (device globals; allocation-free per harness rules)
__device__ float g_Q[(size_t)BH_ * S_ * DK_];   // [bh][s][d]
__device__ float g_K[(size_t)BH_ * S_ * DK_];
__device__ float g_V[(size_t)BH_ * S_ * DK_];
__device__ float g_att[(size_t)M_ * H_];        // [(b*S+s)][h]
__device__ float g_dist_fallback[(size_t)BH_ * S_ * S_];  // 512MB fallback if d_out only holds `out`

// ---------------------------------------------------------------------------
// GEMM: C[r,o] = sum_h A[r,h] * W[o,h]   (A: M_ x 1024 row-major, W: 1024x1024 row-major)
// mode 0: projection scatter  -> out[((head*B+b)*S + s)*64 + d],  r=s*B+b, o=head*64+d
// mode 1: final out transpose -> out[(s*B+b)*H + o],              r=b*S+s
// BM=BN=128, BK=8, 256 threads, 8x8 per thread.
// ---------------------------------------------------------------------------
__global__ __launch_bounds__(256, 1)
void gemm_abT_kernel(const float* __restrict__ A, const float* __restrict__ W,
                     float* __restrict__ out, int mode)
{
    __shared__ float As[8][128];
    __shared__ float Bs[8][128];

    const int tid  = threadIdx.x;
    const int tx   = tid & 15;   // 0..15  (cols)
    const int ty   = tid >> 4;   // 0..15  (rows)
    const int brow = blockIdx.y * 128;
    const int bcol = blockIdx.x * 128;

    const int lrow = tid >> 1;          // 0..127
    const int lcol = (tid & 1) * 4;     // 0 or 4

    const float* Aptr = A + (size_t)(brow + lrow) * H_ + lcol;
    const float* Wptr = W + (size_t)(bcol + lrow) * H_ + lcol;

    float acc[8][8];
#pragma unroll
    for (int i = 0; i < 8; i++)
#pragma unroll
        for (int j = 0; j < 8; j++) acc[i][j] = 0.0f;

    for (int k0 = 0; k0 < H_; k0 += 8) {
        float4 av = *(const float4*)(Aptr + k0);
        float4 bv = *(const float4*)(Wptr + k0);
        As[lcol + 0][lrow] = av.x; As[lcol + 1][lrow] = av.y;
        As[lcol + 2][lrow] = av.z; As[lcol + 3][lrow] = av.w;
        Bs[lcol + 0][lrow] = bv.x; Bs[lcol + 1][lrow] = bv.y;
        Bs[lcol + 2][lrow] = bv.z; Bs[lcol + 3][lrow] = bv.w;
        __syncthreads();
#pragma unroll
        for (int k = 0; k < 8; k++) {
            float ra[8], rb[8];
#pragma unroll
            for (int i = 0; i < 8; i++) ra[i] = As[k][ty * 8 + i];
#pragma unroll
            for (int j = 0; j < 8; j++) rb[j] = Bs[k][tx * 8 + j];
#pragma unroll
            for (int i = 0; i < 8; i++)
#pragma unroll
                for (int j = 0; j < 8; j++)
                    acc[i][j] = fmaf(ra[i], rb[j], acc[i][j]);
        }
        __syncthreads();
    }

#pragma unroll
    for (int i = 0; i < 8; i++) {
        const int r = brow + ty * 8 + i;
#pragma unroll
        for (int j = 0; j < 8; j++) {
            const int o = bcol + tx * 8 + j;
            const float v = acc[i][j];
            if (mode == 0) {
                const int s = r >> 3, b = r & 7;           // r = s*B + b
                const int head = o >> 6, d = o & 63;
                out[(((size_t)(head * B_ + b)) * S_ + s) * DK_ + d] = v;
            } else {
                const int b = r >> 10, s = r & 1023;       // r = b*S + s
                out[((size_t)s * B_ + b) * H_ + o] = v;
            }
        }
    }
}

// ---------------------------------------------------------------------------
// Scores: raw[bh,i,j] = 0.125 * dot(K[bh,i,:], Q[bh,j,:]) ; only tiles with j<=i
// 64x64 tiles over (i,j), K-dim = 64 in 4 steps of 16. Upper-triangular tiles skipped.
// ---------------------------------------------------------------------------
__global__ __launch_bounds__(256, 1)
void scores_kernel(const float* __restrict__ Qb, const float* __restrict__ Kb,
                   float* __restrict__ dist)
{
    const int jb = blockIdx.x;   // 0..15
    const int ib = blockIdx.y;   // 0..15
    const int bh = blockIdx.z;   // 0..127
    if (jb > ib) return;         // fully masked tile: softmax writes zeros there

    __shared__ float Ks[64][17];
    __shared__ float Qs[64][17];

    const float* Kbase = Kb + (size_t)bh * S_ * DK_;
    const float* Qbase = Qb + (size_t)bh * S_ * DK_;

    const int tid  = threadIdx.x;
    const int lrow = tid >> 2;          // 0..63
    const int lcol = (tid & 3) * 4;     // 0,4,8,12
    const int tx   = tid & 15;
    const int ty   = tid >> 4;

    float acc[4][4];
#pragma unroll
    for (int i = 0; i < 4; i++)
#pragma unroll
        for (int j = 0; j < 4; j++) acc[i][j] = 0.0f;

    for (int k0 = 0; k0 < DK_; k0 += 16) {
        float4 kv = *(const float4*)(Kbase + (size_t)(ib * 64 + lrow) * DK_ + k0 + lcol);
        float4 qv = *(const float4*)(Qbase + (size_t)(jb * 64 + lrow) * DK_ + k0 + lcol);
        Ks[lrow][lcol + 0] = kv.x; Ks[lrow][lcol + 1] = kv.y;
        Ks[lrow][lcol + 2] = kv.z; Ks[lrow][lcol + 3] = kv.w;
        Qs[lrow][lcol + 0] = qv.x; Qs[lrow][lcol + 1] = qv.y;
        Qs[lrow][lcol + 2] = qv.z; Qs[lrow][lcol + 3] = qv.w;
        __syncthreads();
#pragma unroll
        for (int k = 0; k < 16; k++) {
            float ra[4], rb[4];
#pragma unroll
            for (int ii = 0; ii < 4; ii++) ra[ii] = Ks[ty * 4 + ii][k];
#pragma unroll
            for (int jj = 0; jj < 4; jj++) rb[jj] = Qs[tx * 4 + jj][k];
#pragma unroll
            for (int ii = 0; ii < 4; ii++)
#pragma unroll
                for (int jj = 0; jj < 4; jj++)
                    acc[ii][jj] = fmaf(ra[ii], rb[jj], acc[ii][jj]);
        }
        __syncthreads();
    }

#pragma unroll
    for (int ii = 0; ii < 4; ii++) {
        const int i = ib * 64 + ty * 4 + ii;
        float* rowp = dist + (size_t)bh * S_ * S_ + (size_t)i * S_ + jb * 64;
#pragma unroll
        for (int jj = 0; jj < 4; jj++)
            rowp[tx * 4 + jj] = acc[ii][jj] * 0.125f;
    }
}

// ---------------------------------------------------------------------------
// Softmax over j (query axis) for each (bh, i), valid range j in [0, i].
// Writes the FULL row: normalized values for j<=i, exact 0 for j>i.
// ---------------------------------------------------------------------------
__global__ __launch_bounds__(256, 1)
void softmax_kernel(float* __restrict__ dist)
{
    const int i  = blockIdx.x;
    const int bh = blockIdx.y;
    float* row = dist + (size_t)bh * S_ * S_ + (size_t)i * S_;
    const int n = i + 1;
    const int tid = threadIdx.x;

    float x[4];
    float mx = -INFINITY;
#pragma unroll
    for (int t = 0; t < 4; t++) {
        const int j = tid + t * 256;
        x[t] = (j < n) ? row[j] : -INFINITY;
        mx = fmaxf(mx, x[t]);
    }
#pragma unroll
    for (int o = 16; o; o >>= 1) mx = fmaxf(mx, __shfl_xor_sync(0xFFFFFFFFu, mx, o));

    __shared__ float red[8];
    if ((tid & 31) == 0) red[tid >> 5] = mx;
    __syncthreads();
    float bmax = red[0];
#pragma unroll
    for (int w = 1; w < 8; w++) bmax = fmaxf(bmax, red[w]);
    __syncthreads();

    float e[4];
    float s = 0.0f;
#pragma unroll
    for (int t = 0; t < 4; t++) {
        const int j = tid + t * 256;
        e[t] = (j < n) ? __expf(x[t] - bmax) : 0.0f;
        s += e[t];
    }
#pragma unroll
    for (int o = 16; o; o >>= 1) s += __shfl_xor_sync(0xFFFFFFFFu, s, o);
    if ((tid & 31) == 0) red[tid >> 5] = s;
    __syncthreads();
    float bsum = red[0];
#pragma unroll
    for (int w = 1; w < 8; w++) bsum += red[w];

    const float inv = 1.0f / bsum;
#pragma unroll
    for (int t = 0; t < 4; t++) {
        const int j = tid + t * 256;
        row[j] = e[t] * inv;
    }
}

// ---------------------------------------------------------------------------
// att[j,bh,d] = sum_i dist[bh,i,j] * V[bh,i,d]; nonzero only for i >= j, so the
// K-loop starts at the tile diagonal. Output scattered to g_att[(b*S+j)][head*64+d].
// ---------------------------------------------------------------------------
__global__ __launch_bounds__(256, 1)
void att_kernel(const float* __restrict__ dist, const float* __restrict__ Vb,
                float* __restrict__ att)
{
    const int jb = blockIdx.x;   // 0..15
    const int bh = blockIdx.y;   // 0..127

    __shared__ float Ds[16][68];
    __shared__ float Vs[16][68];

    const float* dbase = dist + (size_t)bh * S_ * S_;
    const float* vbase = Vb + (size_t)bh * S_ * DK_;

    const int tid  = threadIdx.x;
    const int lrow = tid >> 4;          // 0..15
    const int lcol = (tid & 15) * 4;    // 0..60
    const int tx   = tid & 15;
    const int ty   = tid >> 4;

    float acc[4][4];
#pragma unroll
    for (int i = 0; i < 4; i++)
#pragma unroll
        for (int j = 0; j < 4; j++) acc[i][j] = 0.0f;

    for (int k0 = jb * 64; k0 < S_; k0 += 16) {
        float4 dv = *(const float4*)(dbase + (size_t)(k0 + lrow) * S_ + jb * 64 + lcol);
        float4 vv = *(const float4*)(vbase + (size_t)(k0 + lrow) * DK_ + lcol);
        Ds[lrow][lcol + 0] = dv.x; Ds[lrow][lcol + 1] = dv.y;
        Ds[lrow][lcol + 2] = dv.z; Ds[lrow][lcol + 3] = dv.w;
        Vs[lrow][lcol + 0] = vv.x; Vs[lrow][lcol + 1] = vv.y;
        Vs[lrow][lcol + 2] = vv.z; Vs[lrow][lcol + 3] = vv.w;
        __syncthreads();
#pragma unroll
        for (int k = 0; k < 16; k++) {
            float ra[4], rb[4];
#pragma unroll
            for (int ii = 0; ii < 4; ii++) ra[ii] = Ds[k][ty * 4 + ii];
#pragma unroll
            for (int dd = 0; dd < 4; dd++) rb[dd] = Vs[k][tx * 4 + dd];
#pragma unroll
            for (int ii = 0; ii < 4; ii++)
#pragma unroll
                for (int dd = 0; dd < 4; dd++)
                    acc[ii][dd] = fmaf(ra[ii], rb[dd], acc[ii][dd]);
        }
        __syncthreads();
    }

    const int head = bh >> 3, b = bh & 7;
#pragma unroll
    for (int ii = 0; ii < 4; ii++) {
        const int j = jb * 64 + ty * 4 + ii;
        float* op = att + ((size_t)b * S_ + j) * H_ + head * DK_;
#pragma unroll
        for (int dd = 0; dd < 4; dd++)
            op[tx * 4 + dd] = acc[ii][dd];
    }
}

// ---------------------------------------------------------------------------
extern "C" void kernel_launch(void* const* d_in, const int* in_sizes, int n_in,
                              void* d_out, int out_size)
{
    const float* value = (const float*)d_in[0];
    const float* key   = (const float*)d_in[1];
    const float* query = (const float*)d_in[2];
    const float* Wq    = (const float*)d_in[3];
    const float* Wk    = (const float*)d_in[4];
    const float* Wv    = (const float*)d_in[5];
    const float* Wo    = (const float*)d_in[6];
    float* out = (float*)d_out;

    // scratch pointers via symbols
    float *qp, *kp, *vp, *ap, *distFb;
    cudaGetSymbolAddress((void**)&qp, g_Q);
    cudaGetSymbolAddress((void**)&kp, g_K);
    cudaGetSymbolAddress((void**)&vp, g_V);
    cudaGetSymbolAddress((void**)&ap, g_att);
    cudaGetSymbolAddress((void**)&distFb, g_dist_fallback);

    // dist target: second tuple element lives right after `out` if out_size covers it
    float* dist = ((size_t)out_size >= OUT_ELEMS + DIST_ELEMS) ? (out + OUT_ELEMS) : distFb;

    dim3 gGemm(H_ / 128, M_ / 128);      // (8, 64)

    // Projections
    gemm_abT_kernel<<<gGemm, 256>>>(query, Wq, qp, 0);
    gemm_abT_kernel<<<gGemm, 256>>>(key,   Wk, kp, 0);
    gemm_abT_kernel<<<gGemm, 256>>>(value, Wv, vp, 0);

    // Scores (masked tiles skipped) + softmax over query axis
    scores_kernel<<<dim3(16, 16, BH_), 256>>>(qp, kp, dist);
    softmax_kernel<<<dim3(S_, BH_), 256>>>(dist);

    // att = dist^T @ V per head-batch
    att_kernel<<<dim3(16, BH_), 256>>>(dist, vp, ap);

    // out = att @ Wo^T, written transposed to (S,B,H)
    gemm_abT_kernel<<<gGemm, 256>>>(ap, Wo, out, 1);
}

// round 9
// speedup vs baseline: 1.0026x; 1.0008x over previous
#include <cuda_runtime.h>
#include <cuda_bf16.h>
#include <cstdint>
#include <cstdio>

// Problem constants
#define S_   1024
#define B_   8
#define H_   1024
#define NH_  16
#define DK_  64
#define BH_  (NH_ * B_)        // 128
#define M_   (S_ * B_)         // 8192 rows for projection GEMMs

static const size_t OUT_ELEMS  = (size_t)S_ * B_ * H_;          // 8,388,608
static const size_t DIST_ELEMS = (size_t)BH_ * S_ * S_;         // 134,217,728

// Scratch (device globals; allocation-free per harness rules)
__device__ float g_Q[(size_t)BH_ * S_ * DK_];   // [bh][s][d]
__device__ float g_K[(size_t)BH_ * S_ * DK_];
__device__ float g_V[(size_t)BH_ * S_ * DK_];
__device__ float g_att[(size_t)M_ * H_];        // [(b*S+s)][h]
__device__ float g_dist_fallback[(size_t)BH_ * S_ * S_];  // 512MB fallback if d_out only holds `out`

// ---------------------------------------------------------------------------
// GEMM: C[r,o] = sum_h A[r,h] * W[o,h]   (A: M_ x 1024 row-major, W: 1024x1024 row-major)
// mode 0: projection scatter  -> out[((head*B+b)*S + s)*64 + d],  r=s*B+b, o=head*64+d
// mode 1: final out transpose -> out[(s*B+b)*H + o],              r=b*S+s
// BM=BN=128, BK=8, 256 threads, 8x8 per thread.
// ---------------------------------------------------------------------------
__global__ __launch_bounds__(256, 1)
void gemm_abT_kernel(const float* __restrict__ A, const float* __restrict__ W,
                     float* __restrict__ out, int mode)
{
    __shared__ float As[8][128];
    __shared__ float Bs[8][128];

    const int tid  = threadIdx.x;
    const int tx   = tid & 15;   // 0..15  (cols)
    const int ty   = tid >> 4;   // 0..15  (rows)
    const int brow = blockIdx.y * 128;
    const int bcol = blockIdx.x * 128;

    const int lrow = tid >> 1;          // 0..127
    const int lcol = (tid & 1) * 4;     // 0 or 4

    const float* Aptr = A + (size_t)(brow + lrow) * H_ + lcol;
    const float* Wptr = W + (size_t)(bcol + lrow) * H_ + lcol;

    float acc[8][8];
#pragma unroll
    for (int i = 0; i < 8; i++)
#pragma unroll
        for (int j = 0; j < 8; j++) acc[i][j] = 0.0f;

    for (int k0 = 0; k0 < H_; k0 += 8) {
        float4 av = *(const float4*)(Aptr + k0);
        float4 bv = *(const float4*)(Wptr + k0);
        As[lcol + 0][lrow] = av.x; As[lcol + 1][lrow] = av.y;
        As[lcol + 2][lrow] = av.z; As[lcol + 3][lrow] = av.w;
        Bs[lcol + 0][lrow] = bv.x; Bs[lcol + 1][lrow] = bv.y;
        Bs[lcol + 2][lrow] = bv.z; Bs[lcol + 3][lrow] = bv.w;
        __syncthreads();
#pragma unroll
        for (int k = 0; k < 8; k++) {
            float ra[8], rb[8];
#pragma unroll
            for (int i = 0; i < 8; i++) ra[i] = As[k][ty * 8 + i];
#pragma unroll
            for (int j = 0; j < 8; j++) rb[j] = Bs[k][tx * 8 + j];
#pragma unroll
            for (int i = 0; i < 8; i++)
#pragma unroll
                for (int j = 0; j < 8; j++)
                    acc[i][j] = fmaf(ra[i], rb[j], acc[i][j]);
        }
        __syncthreads();
    }

#pragma unroll
    for (int i = 0; i < 8; i++) {
        const int r = brow + ty * 8 + i;
#pragma unroll
        for (int j = 0; j < 8; j++) {
            const int o = bcol + tx * 8 + j;
            const float v = acc[i][j];
            if (mode == 0) {
                const int s = r >> 3, b = r & 7;           // r = s*B + b
                const int head = o >> 6, d = o & 63;
                out[(((size_t)(head * B_ + b)) * S_ + s) * DK_ + d] = v;
            } else {
                const int b = r >> 10, s = r & 1023;       // r = b*S + s
                out[((size_t)s * B_ + b) * H_ + o] = v;
            }
        }
    }
}

// ---------------------------------------------------------------------------
// Scores: raw[bh,i,j] = 0.125 * dot(K[bh,i,:], Q[bh,j,:]) ; only tiles with j<=i
// 64x64 tiles over (i,j), K-dim = 64 in 4 steps of 16. Upper-triangular tiles skipped.
// ---------------------------------------------------------------------------
__global__ __launch_bounds__(256, 1)
void scores_kernel(const float* __restrict__ Qb, const float* __restrict__ Kb,
                   float* __restrict__ dist)
{
    const int jb = blockIdx.x;   // 0..15
    const int ib = blockIdx.y;   // 0..15
    const int bh = blockIdx.z;   // 0..127
    if (jb > ib) return;         // fully masked tile: softmax writes zeros there

    __shared__ float Ks[64][17];
    __shared__ float Qs[64][17];

    const float* Kbase = Kb + (size_t)bh * S_ * DK_;
    const float* Qbase = Qb + (size_t)bh * S_ * DK_;

    const int tid  = threadIdx.x;
    const int lrow = tid >> 2;          // 0..63
    const int lcol = (tid & 3) * 4;     // 0,4,8,12
    const int tx   = tid & 15;
    const int ty   = tid >> 4;

    float acc[4][4];
#pragma unroll
    for (int i = 0; i < 4; i++)
#pragma unroll
        for (int j = 0; j < 4; j++) acc[i][j] = 0.0f;

    for (int k0 = 0; k0 < DK_; k0 += 16) {
        float4 kv = *(const float4*)(Kbase + (size_t)(ib * 64 + lrow) * DK_ + k0 + lcol);
        float4 qv = *(const float4*)(Qbase + (size_t)(jb * 64 + lrow) * DK_ + k0 + lcol);
        Ks[lrow][lcol + 0] = kv.x; Ks[lrow][lcol + 1] = kv.y;
        Ks[lrow][lcol + 2] = kv.z; Ks[lrow][lcol + 3] = kv.w;
        Qs[lrow][lcol + 0] = qv.x; Qs[lrow][lcol + 1] = qv.y;
        Qs[lrow][lcol + 2] = qv.z; Qs[lrow][lcol + 3] = qv.w;
        __syncthreads();
#pragma unroll
        for (int k = 0; k < 16; k++) {
            float ra[4], rb[4];
#pragma unroll
            for (int ii = 0; ii < 4; ii++) ra[ii] = Ks[ty * 4 + ii][k];
#pragma unroll
            for (int jj = 0; jj < 4; jj++) rb[jj] = Qs[tx * 4 + jj][k];
#pragma unroll
            for (int ii = 0; ii < 4; ii++)
#pragma unroll
                for (int jj = 0; jj < 4; jj++)
                    acc[ii][jj] = fmaf(ra[ii], rb[jj], acc[ii][jj]);
        }
        __syncthreads();
    }

#pragma unroll
    for (int ii = 0; ii < 4; ii++) {
        const int i = ib * 64 + ty * 4 + ii;
        float* rowp = dist + (size_t)bh * S_ * S_ + (size_t)i * S_ + jb * 64;
#pragma unroll
        for (int jj = 0; jj < 4; jj++)
            rowp[tx * 4 + jj] = acc[ii][jj] * 0.125f;
    }
}

// ---------------------------------------------------------------------------
// Softmax over j (query axis) for each (bh, i), valid range j in [0, i].
// Writes the FULL row: normalized values for j<=i, exact 0 for j>i.
// ---------------------------------------------------------------------------
__global__ __launch_bounds__(256, 1)
void softmax_kernel(float* __restrict__ dist)
{
    const int i  = blockIdx.x;
    const int bh = blockIdx.y;
    float* row = dist + (size_t)bh * S_ * S_ + (size_t)i * S_;
    const int n = i + 1;
    const int tid = threadIdx.x;

    float x[4];
    float mx = -INFINITY;
#pragma unroll
    for (int t = 0; t < 4; t++) {
        const int j = tid + t * 256;
        x[t] = (j < n) ? row[j] : -INFINITY;
        mx = fmaxf(mx, x[t]);
    }
#pragma unroll
    for (int o = 16; o; o >>= 1) mx = fmaxf(mx, __shfl_xor_sync(0xFFFFFFFFu, mx, o));

    __shared__ float red[8];
    if ((tid & 31) == 0) red[tid >> 5] = mx;
    __syncthreads();
    float bmax = red[0];
#pragma unroll
    for (int w = 1; w < 8; w++) bmax = fmaxf(bmax, red[w]);
    __syncthreads();

    float e[4];
    float s = 0.0f;
#pragma unroll
    for (int t = 0; t < 4; t++) {
        const int j = tid + t * 256;
        e[t] = (j < n) ? __expf(x[t] - bmax) : 0.0f;
        s += e[t];
    }
#pragma unroll
    for (int o = 16; o; o >>= 1) s += __shfl_xor_sync(0xFFFFFFFFu, s, o);
    if ((tid & 31) == 0) red[tid >> 5] = s;
    __syncthreads();
    float bsum = red[0];
#pragma unroll
    for (int w = 1; w < 8; w++) bsum += red[w];

    const float inv = 1.0f / bsum;
#pragma unroll
    for (int t = 0; t < 4; t++) {
        const int j = tid + t * 256;
        row[j] = e[t] * inv;
    }
}

// ---------------------------------------------------------------------------
// att[j,bh,d] = sum_i dist[bh,i,j] * V[bh,i,d]; nonzero only for i >= j, so the
// K-loop starts at the tile diagonal. Output scattered to g_att[(b*S+j)][head*64+d].
// ---------------------------------------------------------------------------
__global__ __launch_bounds__(256, 1)
void att_kernel(const float* __restrict__ dist, const float* __restrict__ Vb,
                float* __restrict__ att)
{
    const int jb = blockIdx.x;   // 0..15
    const int bh = blockIdx.y;   // 0..127

    __shared__ float Ds[16][68];
    __shared__ float Vs[16][68];

    const float* dbase = dist + (size_t)bh * S_ * S_;
    const float* vbase = Vb + (size_t)bh * S_ * DK_;

    const int tid  = threadIdx.x;
    const int lrow = tid >> 4;          // 0..15
    const int lcol = (tid & 15) * 4;    // 0..60
    const int tx   = tid & 15;
    const int ty   = tid >> 4;

    float acc[4][4];
#pragma unroll
    for (int i = 0; i < 4; i++)
#pragma unroll
        for (int j = 0; j < 4; j++) acc[i][j] = 0.0f;

    for (int k0 = jb * 64; k0 < S_; k0 += 16) {
        float4 dv = *(const float4*)(dbase + (size_t)(k0 + lrow) * S_ + jb * 64 + lcol);
        float4 vv = *(const float4*)(vbase + (size_t)(k0 + lrow) * DK_ + lcol);
        Ds[lrow][lcol + 0] = dv.x; Ds[lrow][lcol + 1] = dv.y;
        Ds[lrow][lcol + 2] = dv.z; Ds[lrow][lcol + 3] = dv.w;
        Vs[lrow][lcol + 0] = vv.x; Vs[lrow][lcol + 1] = vv.y;
        Vs[lrow][lcol + 2] = vv.z; Vs[lrow][lcol + 3] = vv.w;
        __syncthreads();
#pragma unroll
        for (int k = 0; k < 16; k++) {
            float ra[4], rb[4];
#pragma unroll
            for (int ii = 0; ii < 4; ii++) ra[ii] = Ds[k][ty * 4 + ii];
#pragma unroll
            for (int dd = 0; dd < 4; dd++) rb[dd] = Vs[k][tx * 4 + dd];
#pragma unroll
            for (int ii = 0; ii < 4; ii++)
#pragma unroll
                for (int dd = 0; dd < 4; dd++)
                    acc[ii][dd] = fmaf(ra[ii], rb[dd], acc[ii][dd]);
        }
        __syncthreads();
    }

    const int head = bh >> 3, b = bh & 7;
#pragma unroll
    for (int ii = 0; ii < 4; ii++) {
        const int j = jb * 64 + ty * 4 + ii;
        float* op = att + ((size_t)b * S_ + j) * H_ + head * DK_;
#pragma unroll
        for (int dd = 0; dd < 4; dd++)
            op[tx * 4 + dd] = acc[ii][dd];
    }
}

// ---------------------------------------------------------------------------
extern "C" void kernel_launch(void* const* d_in, const int* in_sizes, int n_in,
                              void* d_out, int out_size)
{
    const float* value = (const float*)d_in[0];
    const float* key   = (const float*)d_in[1];
    const float* query = (const float*)d_in[2];
    const float* Wq    = (const float*)d_in[3];
    const float* Wk    = (const float*)d_in[4];
    const float* Wv    = (const float*)d_in[5];
    const float* Wo    = (const float*)d_in[6];
    float* out = (float*)d_out;

    // scratch pointers via symbols
    float *qp, *kp, *vp, *ap, *distFb;
    cudaGetSymbolAddress((void**)&qp, g_Q);
    cudaGetSymbolAddress((void**)&kp, g_K);
    cudaGetSymbolAddress((void**)&vp, g_V);
    cudaGetSymbolAddress((void**)&ap, g_att);
    cudaGetSymbolAddress((void**)&distFb, g_dist_fallback);

    // dist target: second tuple element lives right after `out` if out_size covers it
    float* dist = ((size_t)out_size >= OUT_ELEMS + DIST_ELEMS) ? (out + OUT_ELEMS) : distFb;

    dim3 gGemm(H_ / 128, M_ / 128);      // (8, 64)

    // Projections
    gemm_abT_kernel<<<gGemm, 256>>>(query, Wq, qp, 0);
    gemm_abT_kernel<<<gGemm, 256>>>(key,   Wk, kp, 0);
    gemm_abT_kernel<<<gGemm, 256>>>(value, Wv, vp, 0);

    // Scores (masked tiles skipped) + softmax over query axis
    scores_kernel<<<dim3(16, 16, BH_), 256>>>(qp, kp, dist);
    softmax_kernel<<<dim3(S_, BH_), 256>>>(dist);

    // att = dist^T @ V per head-batch
    att_kernel<<<dim3(16, BH_), 256>>>(dist, vp, ap);

    // out = att @ Wo^T, written transposed to (S,B,H)
    gemm_abT_kernel<<<gGemm, 256>>>(ap, Wo, out, 1);
}

// round 10
// speedup vs baseline: 1.0039x; 1.0012x over previous
#include <cuda_runtime.h>
#include <cuda_bf16.h>
#include <cstdint>
#include <cstdio>

// Problem constants
#define S_   1024
#define B_   8
#define H_   1024
#define NH_  16
#define DK_  64
#define BH_  (NH_ * B_)        // 128
#define M_   (S_ * B_)         // 8192 rows for projection GEMMs

static const size_t OUT_ELEMS  = (size_t)S_ * B_ * H_;          // 8,388,608
static const size_t DIST_ELEMS = (size_t)BH_ * S_ * S_;         // 134,217,728

// Scratch (device globals; allocation-free per harness rules)
__device__ float g_Q[(size_t)BH_ * S_ * DK_];   // [bh][s][d]
__device__ float g_K[(size_t)BH_ * S_ * DK_];
__device__ float g_V[(size_t)BH_ * S_ * DK_];
__device__ float g_att[(size_t)M_ * H_];        // [(b*S+s)][h]
__device__ float g_dist_fallback[(size_t)BH_ * S_ * S_];  // 512MB fallback if d_out only holds `out`

// ---------------------------------------------------------------------------
// GEMM: C[r,o] = sum_h A[r,h] * W[o,h]   (A: M_ x 1024 row-major, W: 1024x1024 row-major)
// mode 0: projection scatter  -> out[((head*B+b)*S + s)*64 + d],  r=s*B+b, o=head*64+d
// mode 1: final out transpose -> out[(s*B+b)*H + o],              r=b*S+s
// BM=BN=128, BK=8, 256 threads, 8x8 per thread.
// ---------------------------------------------------------------------------
__global__ __launch_bounds__(256, 1)
void gemm_abT_kernel(const float* __restrict__ A, const float* __restrict__ W,
                     float* __restrict__ out, int mode)
{
    __shared__ float As[8][128];
    __shared__ float Bs[8][128];

    const int tid  = threadIdx.x;
    const int tx   = tid & 15;   // 0..15  (cols)
    const int ty   = tid >> 4;   // 0..15  (rows)
    const int brow = blockIdx.y * 128;
    const int bcol = blockIdx.x * 128;

    const int lrow = tid >> 1;          // 0..127
    const int lcol = (tid & 1) * 4;     // 0 or 4

    const float* Aptr = A + (size_t)(brow + lrow) * H_ + lcol;
    const float* Wptr = W + (size_t)(bcol + lrow) * H_ + lcol;

    float acc[8][8];
#pragma unroll
    for (int i = 0; i < 8; i++)
#pragma unroll
        for (int j = 0; j < 8; j++) acc[i][j] = 0.0f;

    for (int k0 = 0; k0 < H_; k0 += 8) {
        float4 av = *(const float4*)(Aptr + k0);
        float4 bv = *(const float4*)(Wptr + k0);
        As[lcol + 0][lrow] = av.x; As[lcol + 1][lrow] = av.y;
        As[lcol + 2][lrow] = av.z; As[lcol + 3][lrow] = av.w;
        Bs[lcol + 0][lrow] = bv.x; Bs[lcol + 1][lrow] = bv.y;
        Bs[lcol + 2][lrow] = bv.z; Bs[lcol + 3][lrow] = bv.w;
        __syncthreads();
#pragma unroll
        for (int k = 0; k < 8; k++) {
            float ra[8], rb[8];
#pragma unroll
            for (int i = 0; i < 8; i++) ra[i] = As[k][ty * 8 + i];
#pragma unroll
            for (int j = 0; j < 8; j++) rb[j] = Bs[k][tx * 8 + j];
#pragma unroll
            for (int i = 0; i < 8; i++)
#pragma unroll
                for (int j = 0; j < 8; j++)
                    acc[i][j] = fmaf(ra[i], rb[j], acc[i][j]);
        }
        __syncthreads();
    }

#pragma unroll
    for (int i = 0; i < 8; i++) {
        const int r = brow + ty * 8 + i;
#pragma unroll
        for (int j = 0; j < 8; j++) {
            const int o = bcol + tx * 8 + j;
            const float v = acc[i][j];
            if (mode == 0) {
                const int s = r >> 3, b = r & 7;           // r = s*B + b
                const int head = o >> 6, d = o & 63;
                out[(((size_t)(head * B_ + b)) * S_ + s) * DK_ + d] = v;
            } else {
                const int b = r >> 10, s = r & 1023;       // r = b*S + s
                out[((size_t)s * B_ + b) * H_ + o] = v;
            }
        }
    }
}

// ---------------------------------------------------------------------------
// Scores: raw[bh,i,j] = 0.125 * dot(K[bh,i,:], Q[bh,j,:]) ; only tiles with j<=i
// 64x64 tiles over (i,j), K-dim = 64 in 4 steps of 16. Upper-triangular tiles skipped.
// ---------------------------------------------------------------------------
__global__ __launch_bounds__(256, 1)
void scores_kernel(const float* __restrict__ Qb, const float* __restrict__ Kb,
                   float* __restrict__ dist)
{
    const int jb = blockIdx.x;   // 0..15
    const int ib = blockIdx.y;   // 0..15
    const int bh = blockIdx.z;   // 0..127
    if (jb > ib) return;         // fully masked tile: softmax writes zeros there

    __shared__ float Ks[64][17];
    __shared__ float Qs[64][17];

    const float* Kbase = Kb + (size_t)bh * S_ * DK_;
    const float* Qbase = Qb + (size_t)bh * S_ * DK_;

    const int tid  = threadIdx.x;
    const int lrow = tid >> 2;          // 0..63
    const int lcol = (tid & 3) * 4;     // 0,4,8,12
    const int tx   = tid & 15;
    const int ty   = tid >> 4;

    float acc[4][4];
#pragma unroll
    for (int i = 0; i < 4; i++)
#pragma unroll
        for (int j = 0; j < 4; j++) acc[i][j] = 0.0f;

    for (int k0 = 0; k0 < DK_; k0 += 16) {
        float4 kv = *(const float4*)(Kbase + (size_t)(ib * 64 + lrow) * DK_ + k0 + lcol);
        float4 qv = *(const float4*)(Qbase + (size_t)(jb * 64 + lrow) * DK_ + k0 + lcol);
        Ks[lrow][lcol + 0] = kv.x; Ks[lrow][lcol + 1] = kv.y;
        Ks[lrow][lcol + 2] = kv.z; Ks[lrow][lcol + 3] = kv.w;
        Qs[lrow][lcol + 0] = qv.x; Qs[lrow][lcol + 1] = qv.y;
        Qs[lrow][lcol + 2] = qv.z; Qs[lrow][lcol + 3] = qv.w;
        __syncthreads();
#pragma unroll
        for (int k = 0; k < 16; k++) {
            float ra[4], rb[4];
#pragma unroll
            for (int ii = 0; ii < 4; ii++) ra[ii] = Ks[ty * 4 + ii][k];
#pragma unroll
            for (int jj = 0; jj < 4; jj++) rb[jj] = Qs[tx * 4 + jj][k];
#pragma unroll
            for (int ii = 0; ii < 4; ii++)
#pragma unroll
                for (int jj = 0; jj < 4; jj++)
                    acc[ii][jj] = fmaf(ra[ii], rb[jj], acc[ii][jj]);
        }
        __syncthreads();
    }

#pragma unroll
    for (int ii = 0; ii < 4; ii++) {
        const int i = ib * 64 + ty * 4 + ii;
        float* rowp = dist + (size_t)bh * S_ * S_ + (size_t)i * S_ + jb * 64;
#pragma unroll
        for (int jj = 0; jj < 4; jj++)
            rowp[tx * 4 + jj] = acc[ii][jj] * 0.125f;
    }
}

// ---------------------------------------------------------------------------
// Softmax over j (query axis) for each (bh, i), valid range j in [0, i].
// Writes the FULL row: normalized values for j<=i, exact 0 for j>i.
// ---------------------------------------------------------------------------
__global__ __launch_bounds__(256, 1)
void softmax_kernel(float* __restrict__ dist)
{
    const int i  = blockIdx.x;
    const int bh = blockIdx.y;
    float* row = dist + (size_t)bh * S_ * S_ + (size_t)i * S_;
    const int n = i + 1;
    const int tid = threadIdx.x;

    float x[4];
    float mx = -INFINITY;
#pragma unroll
    for (int t = 0; t < 4; t++) {
        const int j = tid + t * 256;
        x[t] = (j < n) ? row[j] : -INFINITY;
        mx = fmaxf(mx, x[t]);
    }
#pragma unroll
    for (int o = 16; o; o >>= 1) mx = fmaxf(mx, __shfl_xor_sync(0xFFFFFFFFu, mx, o));

    __shared__ float red[8];
    if ((tid & 31) == 0) red[tid >> 5] = mx;
    __syncthreads();
    float bmax = red[0];
#pragma unroll
    for (int w = 1; w < 8; w++) bmax = fmaxf(bmax, red[w]);
    __syncthreads();

    float e[4];
    float s = 0.0f;
#pragma unroll
    for (int t = 0; t < 4; t++) {
        const int j = tid + t * 256;
        e[t] = (j < n) ? __expf(x[t] - bmax) : 0.0f;
        s += e[t];
    }
#pragma unroll
    for (int o = 16; o; o >>= 1) s += __shfl_xor_sync(0xFFFFFFFFu, s, o);
    if ((tid & 31) == 0) red[tid >> 5] = s;
    __syncthreads();
    float bsum = red[0];
#pragma unroll
    for (int w = 1; w < 8; w++) bsum += red[w];

    const float inv = 1.0f / bsum;
#pragma unroll
    for (int t = 0; t < 4; t++) {
        const int j = tid + t * 256;
        row[j] = e[t] * inv;
    }
}

// ---------------------------------------------------------------------------
// att[j,bh,d] = sum_i dist[bh,i,j] * V[bh,i,d]; nonzero only for i >= j, so the
// K-loop starts at the tile diagonal. Output scattered to g_att[(b*S+j)][head*64+d].
// ---------------------------------------------------------------------------
__global__ __launch_bounds__(256, 1)
void att_kernel(const float* __restrict__ dist, const float* __restrict__ Vb,
                float* __restrict__ att)
{
    const int jb = blockIdx.x;   // 0..15
    const int bh = blockIdx.y;   // 0..127

    __shared__ float Ds[16][68];
    __shared__ float Vs[16][68];

    const float* dbase = dist + (size_t)bh * S_ * S_;
    const float* vbase = Vb + (size_t)bh * S_ * DK_;

    const int tid  = threadIdx.x;
    const int lrow = tid >> 4;          // 0..15
    const int lcol = (tid & 15) * 4;    // 0..60
    const int tx   = tid & 15;
    const int ty   = tid >> 4;

    float acc[4][4];
#pragma unroll
    for (int i = 0; i < 4; i++)
#pragma unroll
        for (int j = 0; j < 4; j++) acc[i][j] = 0.0f;

    for (int k0 = jb * 64; k0 < S_; k0 += 16) {
        float4 dv = *(const float4*)(dbase + (size_t)(k0 + lrow) * S_ + jb * 64 + lcol);
        float4 vv = *(const float4*)(vbase + (size_t)(k0 + lrow) * DK_ + lcol);
        Ds[lrow][lcol + 0] = dv.x; Ds[lrow][lcol + 1] = dv.y;
        Ds[lrow][lcol + 2] = dv.z; Ds[lrow][lcol + 3] = dv.w;
        Vs[lrow][lcol + 0] = vv.x; Vs[lrow][lcol + 1] = vv.y;
        Vs[lrow][lcol + 2] = vv.z; Vs[lrow][lcol + 3] = vv.w;
        __syncthreads();
#pragma unroll
        for (int k = 0; k < 16; k++) {
            float ra[4], rb[4];
#pragma unroll
            for (int ii = 0; ii < 4; ii++) ra[ii] = Ds[k][ty * 4 + ii];
#pragma unroll
            for (int dd = 0; dd < 4; dd++) rb[dd] = Vs[k][tx * 4 + dd];
#pragma unroll
            for (int ii = 0; ii < 4; ii++)
#pragma unroll
                for (int dd = 0; dd < 4; dd++)
                    acc[ii][dd] = fmaf(ra[ii], rb[dd], acc[ii][dd]);
        }
        __syncthreads();
    }

    const int head = bh >> 3, b = bh & 7;
#pragma unroll
    for (int ii = 0; ii < 4; ii++) {
        const int j = jb * 64 + ty * 4 + ii;
        float* op = att + ((size_t)b * S_ + j) * H_ + head * DK_;
#pragma unroll
        for (int dd = 0; dd < 4; dd++)
            op[tx * 4 + dd] = acc[ii][dd];
    }
}

// ---------------------------------------------------------------------------
extern "C" void kernel_launch(void* const* d_in, const int* in_sizes, int n_in,
                              void* d_out, int out_size)
{
    const float* value = (const float*)d_in[0];
    const float* key   = (const float*)d_in[1];
    const float* query = (const float*)d_in[2];
    const float* Wq    = (const float*)d_in[3];
    const float* Wk    = (const float*)d_in[4];
    const float* Wv    = (const float*)d_in[5];
    const float* Wo    = (const float*)d_in[6];
    float* out = (float*)d_out;

    // scratch pointers via symbols
    float *qp, *kp, *vp, *ap, *distFb;
    cudaGetSymbolAddress((void**)&qp, g_Q);
    cudaGetSymbolAddress((void**)&kp, g_K);
    cudaGetSymbolAddress((void**)&vp, g_V);
    cudaGetSymbolAddress((void**)&ap, g_att);
    cudaGetSymbolAddress((void**)&distFb, g_dist_fallback);

    // dist target: second tuple element lives right after `out` if out_size covers it
    float* dist = ((size_t)out_size >= OUT_ELEMS + DIST_ELEMS) ? (out + OUT_ELEMS) : distFb;

    dim3 gGemm(H_ / 128, M_ / 128);      // (8, 64)

    // Projections
    gemm_abT_kernel<<<gGemm, 256>>>(query, Wq, qp, 0);
    gemm_abT_kernel<<<gGemm, 256>>>(key,   Wk, kp, 0);
    gemm_abT_kernel<<<gGemm, 256>>>(value, Wv, vp, 0);

    // Scores (masked tiles skipped) + softmax over query axis
    scores_kernel<<<dim3(16, 16, BH_), 256>>>(qp, kp, dist);
    softmax_kernel<<<dim3(S_, BH_), 256>>>(dist);

    // att = dist^T @ V per head-batch
    att_kernel<<<dim3(16, BH_), 256>>>(dist, vp, ap);

    // out = att @ Wo^T, written transposed to (S,B,H)
    gemm_abT_kernel<<<gGemm, 256>>>(ap, Wo, out, 1);
}